// round 7
// baseline (speedup 1.0000x reference)
#include <cuda_runtime.h>
#include <cuda_bf16.h>

typedef unsigned long long ull;

// ---------------- packed f32x2 helpers (sm_103a) ----------------
__device__ __forceinline__ ull pk2(float a, float b){
    ull r; asm("mov.b64 %0,{%1,%2};" : "=l"(r) : "f"(a), "f"(b)); return r;
}
__device__ __forceinline__ void upk2(ull v, float& a, float& b){
    asm("mov.b64 {%0,%1},%2;" : "=f"(a), "=f"(b) : "l"(v));
}
__device__ __forceinline__ ull mul2(ull a, ull b){
    ull r; asm("mul.rn.f32x2 %0,%1,%2;" : "=l"(r) : "l"(a), "l"(b)); return r;
}
__device__ __forceinline__ void fma2(ull& d, ull a, ull b){
    asm("fma.rn.f32x2 %0,%1,%2,%0;" : "+l"(d) : "l"(a), "l"(b));
}
__device__ __forceinline__ void lds2u64(unsigned addr, ull& x, ull& y){
    asm volatile("ld.shared.v2.b64 {%0,%1},[%2];" : "=l"(x), "=l"(y) : "r"(addr));
}

// Tile: 4 rows x 32 cols x all 64 channels. 512 threads = 16 warps.
// smem: xs[c][r][s]  c*240 + r*40 + s   (6 rows, s=3..36 used) : 15360 floats
//       Hs[o][pair]  (ull) at float offset 15360                : 8192 floats
#define XS_FLOATS 15360
#define SMEM_BYTES 94208

// k-step of the inner product over the 3x3 kernel (K = i*3+j, constants only)
#define KS(W,K) { float s_=__shfl_sync(0xffffffffu,(W)[K],oo); ull w_=pk2(s_,s_); \
                  fma2(tA,w_,P[(K)/3][(K)%3]); fma2(tB,w_,P[(K)/3][(K)%3+2]); }

// one 32-o half of the stage-C loop; W = 9 per-lane weight regs (o = base+lane)
#define CHALF(W) \
    _Pragma("unroll 8") \
    for(int oo=0; oo<32; ++oo){ \
        ull hhA, hhB; lds2u64(hs_addr, hhA, hhB); hs_addr += 512; \
        float s0_=__shfl_sync(0xffffffffu,(W)[0],oo); ull w0_=pk2(s0_,s0_); \
        ull tA=mul2(w0_,P[0][0]); ull tB=mul2(w0_,P[0][2]); \
        KS(W,1) KS(W,2) KS(W,3) KS(W,4) KS(W,5) KS(W,6) KS(W,7) KS(W,8) \
        fma2(accA,hhA,tA); fma2(accB,hhB,tB); \
    }

__global__ void __launch_bounds__(512, 1)
invol_kernel(const float* __restrict__ x, const float* __restrict__ w1,
             const float* __restrict__ w2, float* __restrict__ out)
{
    extern __shared__ float sm[];
    const unsigned smem_u32 = (unsigned)__cvta_generic_to_shared(sm);

    const int tid = threadIdx.x;
    const int L   = tid & 31;          // lane
    const int wid = tid >> 5;          // warp 0..15
    const int w0  = blockIdx.x * 32;   // tile col origin
    const int h0  = blockIdx.y * 4;    // tile row origin
    const int b   = blockIdx.z;

    const int ro = L >> 3;             // lane's tile row (0..3)
    const int cb = (L & 7) * 4;        // lane's tile col base (0,4,...,28)

    const float* xb = x + (size_t)b * 64 * 224 * 224;

    // ---------------- Stage A: load 64c x 6r x 34col halo into xs ----------
    for (int row = wid; row < 384; row += 16) {
        int c = row / 6, r = row - 6 * c;
        int gr = h0 - 1 + r;
        bool rok = ((unsigned)gr < 224u);
        const float* src = xb + ((size_t)c * 224 + gr) * 224;
        float* dst = sm + c * 240 + r * 40 + 3;   // s = 3 + i
        #pragma unroll
        for (int ii = 0; ii < 2; ++ii) {
            int i = L + 32 * ii;
            if (i < 34) {
                int g = w0 - 1 + i;
                float v = (rok && (unsigned)g < 224u) ? __ldg(src + g) : 0.0f;
                dst[i] = v;
            }
        }
    }
    __syncthreads();

    // ---------------- Stage B: h[o,p] = relu(sum_c w1[o,c]*x[c,p]) ----------
    // warp wid computes o in {wid, wid+16, wid+32, wid+48}; lane = 4 pixels.
    float w1v0[4], w1v1[4];
    #pragma unroll
    for (int oi = 0; oi < 4; ++oi) {
        int o = wid + 16 * oi;
        w1v0[oi] = __ldg(w1 + o * 64 + L);
        w1v1[oi] = __ldg(w1 + o * 64 + 32 + L);
    }
    ull hA[4], hB[4];
    #pragma unroll
    for (int oi = 0; oi < 4; ++oi) { hA[oi] = 0ull; hB[oi] = 0ull; }

    // center row of lane's pixels: xs r = ro+1, s = 4+cb  (16B aligned)
    const unsigned xrow = smem_u32 + ((ro + 1) * 40 + 4 + cb) * 4;
    #pragma unroll 8
    for (int cc = 0; cc < 32; ++cc) {
        ull xA, xB; lds2u64(xrow + cc * 960, xA, xB);
        #pragma unroll
        for (int oi = 0; oi < 4; ++oi) {
            float s = __shfl_sync(0xffffffffu, w1v0[oi], cc);
            ull ww = pk2(s, s);
            fma2(hA[oi], ww, xA); fma2(hB[oi], ww, xB);
        }
    }
    #pragma unroll 8
    for (int cc = 0; cc < 32; ++cc) {
        ull xA, xB; lds2u64(xrow + 32 * 960 + cc * 960, xA, xB);
        #pragma unroll
        for (int oi = 0; oi < 4; ++oi) {
            float s = __shfl_sync(0xffffffffu, w1v1[oi], cc);
            ull ww = pk2(s, s);
            fma2(hA[oi], ww, xA); fma2(hB[oi], ww, xB);
        }
    }
    // relu + store Hs[o][2L], Hs[o][2L+1]
    ull* Hs = (ull*)(sm + XS_FLOATS);
    #pragma unroll
    for (int oi = 0; oi < 4; ++oi) {
        int o = wid + 16 * oi;
        float a0, a1, a2, a3;
        upk2(hA[oi], a0, a1); upk2(hB[oi], a2, a3);
        a0 = fmaxf(a0, 0.0f); a1 = fmaxf(a1, 0.0f);
        a2 = fmaxf(a2, 0.0f); a3 = fmaxf(a3, 0.0f);
        Hs[o * 64 + 2 * L]     = pk2(a0, a1);
        Hs[o * 64 + 2 * L + 1] = pk2(a2, a3);
    }
    __syncthreads();

    // ---------------- Stage C: out[c,p] = sum_o h[o,p] * (sum_k w2*patch) ---
    // warp wid handles channels c = ci*16 + wid, ci = 0..3
    const unsigned hs_base = smem_u32 + XS_FLOATS * 4 + 2 * L * 8; // Hs + 16B*L
    for (int ci = 0; ci < 4; ++ci) {
        const int c = ci * 16 + wid;

        // per-lane weight slices: wlo[k] = w2[(c*9+k)*64 + L], whi = o=L+32
        const float* w2c = w2 + (size_t)(c * 9) * 64 + L;
        float wlo[9], whi[9];
        #pragma unroll
        for (int k = 0; k < 9; ++k) {
            wlo[k] = __ldg(w2c + k * 64);
            whi[k] = __ldg(w2c + k * 64 + 32);
        }

        // patches: rows ro..ro+2, 6 values v[m] at s0 = 3+cb; packs P[i][m]=(v[m],v[m+1])
        ull P[3][5];
        #pragma unroll
        for (int i = 0; i < 3; ++i) {
            const float* pr = sm + c * 240 + (ro + i) * 40 + 3 + cb;
            float v0 = pr[0], v1 = pr[1], v2 = pr[2];
            float v3 = pr[3], v4 = pr[4], v5 = pr[5];
            P[i][0] = pk2(v0, v1); P[i][1] = pk2(v1, v2); P[i][2] = pk2(v2, v3);
            P[i][3] = pk2(v3, v4); P[i][4] = pk2(v4, v5);
        }

        ull accA = 0ull, accB = 0ull;
        unsigned hs_addr = hs_base;
        CHALF(wlo)   // o = 0..31
        CHALF(whi)   // o = 32..63

        float o0, o1, o2, o3;
        upk2(accA, o0, o1); upk2(accB, o2, o3);
        float4 ov; ov.x = o0; ov.y = o1; ov.z = o2; ov.w = o3;
        size_t obase = (((size_t)(b * 64 + c) * 224 + (h0 + ro)) * 224) + (w0 + cb);
        *(float4*)(out + obase) = ov;
    }
}

extern "C" void kernel_launch(void* const* d_in, const int* in_sizes, int n_in,
                              void* d_out, int out_size)
{
    const float* x  = (const float*)d_in[0];   // (4,64,224,224)
    const float* w1 = (const float*)d_in[1];   // (64,64)
    const float* w2 = (const float*)d_in[2];   // (576,64)
    float* out = (float*)d_out;                // (4,64,224,224)

    cudaFuncSetAttribute(invol_kernel,
                         cudaFuncAttributeMaxDynamicSharedMemorySize, SMEM_BYTES);
    dim3 grid(224 / 32, 224 / 4, 4);           // 7 x 56 x 4 = 1568 blocks
    invol_kernel<<<grid, 512, SMEM_BYTES>>>(x, w1, w2, out);
}